// round 7
// baseline (speedup 1.0000x reference)
#include <cuda_runtime.h>
#include <cuda_fp16.h>
#include <cuda_fp8.h>
#include <cstdint>

// WaveletGatedNet (sm_100 plain): mixed fp8/fp16 split GEMM on mma.sync.
//   logits = Ah*Wh (fp16, K=512)  +  2^-12 * { [Al*2^12|Ah] . [Wh|Wl*2^12] } (fp8 e4m3, K=1024)
// Equivalent MMA cost 64 units vs 96 for bf16x3. Residual logit err ~5e-5.

#define KD 512
#define TPB 256
#define M_TOTAL 16384
#define NKITER 16                 // 8 fp8 iters (K=1024, 128B/row) + 8 fp16 iters (K=512)
#define RSTRIDE 144               // bytes per smem row (128 data + 16 pad)
#define STAGE_BYTES (2 * 128 * RSTRIDE)       // A + B tiles (36864)
#define DSMEM_BYTES (3 * STAGE_BYTES)         // 110592 (> epilogue's 66560)

__device__ __half  g_Ah[(size_t)M_TOTAL * 1024];  // [row][0:512)=Ah, [512:1024)=Al (fp16)
__device__ uint8_t g_A8[(size_t)M_TOTAL * 1024];  // [row][0:512)=e4m3(Al*2^12), [512:1024)=e4m3(Ah)
__device__ __half  g_Bh[(size_t)KD * 512];        // [n][k] = Wh fp16
__device__ uint8_t g_B8[(size_t)KD * 1024];       // [n][0:512)=e4m3(Wh), [512:1024)=e4m3(Wl*2^12)

static __device__ __forceinline__ uint32_t smem_u32(const void* p) {
    uint32_t a;
    asm("{ .reg .u64 t; cvta.to.shared.u64 t, %1; cvt.u32.u64 %0, t; }"
        : "=r"(a) : "l"(p));
    return a;
}
static __device__ __forceinline__ void cp16(uint32_t dst, const void* src) {
    asm volatile("cp.async.cg.shared.global [%0], [%1], 16;"
                 :: "r"(dst), "l"(__cvta_generic_to_global(src)) : "memory");
}
static __device__ __forceinline__ void ldm_x4(uint32_t& r0, uint32_t& r1,
                                              uint32_t& r2, uint32_t& r3, uint32_t a) {
    asm volatile("ldmatrix.sync.aligned.m8n8.x4.shared.b16 {%0,%1,%2,%3}, [%4];"
                 : "=r"(r0), "=r"(r1), "=r"(r2), "=r"(r3) : "r"(a));
}
static __device__ __forceinline__ void mma_f16(float* c, const uint32_t* a,
                                               uint32_t b0, uint32_t b1) {
    asm volatile("mma.sync.aligned.m16n8k16.row.col.f32.f16.f16.f32 "
                 "{%0,%1,%2,%3}, {%4,%5,%6,%7}, {%8,%9}, {%0,%1,%2,%3};"
                 : "+f"(c[0]), "+f"(c[1]), "+f"(c[2]), "+f"(c[3])
                 : "r"(a[0]), "r"(a[1]), "r"(a[2]), "r"(a[3]), "r"(b0), "r"(b1));
}
static __device__ __forceinline__ void mma_f8(float* c, const uint32_t* a,
                                              uint32_t b0, uint32_t b1) {
    asm volatile("mma.sync.aligned.m16n8k32.row.col.f32.e4m3.e4m3.f32 "
                 "{%0,%1,%2,%3}, {%4,%5,%6,%7}, {%8,%9}, {%0,%1,%2,%3};"
                 : "+f"(c[0]), "+f"(c[1]), "+f"(c[2]), "+f"(c[3])
                 : "r"(a[0]), "r"(a[1]), "r"(a[2]), "r"(a[3]), "r"(b0), "r"(b1));
}
static __device__ __forceinline__ uint8_t to_e4m3(float f) {
    return (uint8_t)__nv_cvt_float_to_fp8(f, __NV_SATFINITE, __NV_E4M3);
}

// ---------------------------------------------------------------------------
// Kernel 1: Haar WPT + fp16 hi/lo split + fp8 correction operands.
// ---------------------------------------------------------------------------
__global__ __launch_bounds__(256) void wpt_split_kernel(const float* __restrict__ x) {
    const float s = 0.70710678118654752440f;
    int t = blockIdx.x * blockDim.x + threadIdx.x;
    int bc = t >> 9, d = t & 511;

    const float4* xp = (const float4*)(x + (size_t)bc * 4096 + (size_t)d * 8);
    float4 v0 = xp[0], v1 = xp[1];

    float a0 = (v0.x + v0.y) * s, d0 = (v0.x - v0.y) * s;
    float a1 = (v0.z + v0.w) * s, d1 = (v0.z - v0.w) * s;
    float a2 = (v1.x + v1.y) * s, d2 = (v1.x - v1.y) * s;
    float a3 = (v1.z + v1.w) * s, d3 = (v1.z - v1.w) * s;
    float aa0 = (a0 + a1) * s, da0 = (a0 - a1) * s;
    float aa1 = (a2 + a3) * s, da1 = (a2 - a3) * s;
    float ad0 = (d0 + d1) * s, dd0 = (d0 - d1) * s;
    float ad1 = (d2 + d3) * s, dd1 = (d2 - d3) * s;
    float cc[8];
    cc[0] = (aa0 + aa1) * s; cc[1] = (aa0 - aa1) * s;
    cc[2] = (da0 + da1) * s; cc[3] = (da0 - da1) * s;
    cc[4] = (ad0 + ad1) * s; cc[5] = (ad0 - ad1) * s;
    cc[6] = (dd0 + dd1) * s; cc[7] = (dd0 - dd1) * s;

    __half*  oh = g_Ah + (size_t)(bc * 8) * 1024 + d;
    uint8_t* o8 = g_A8 + (size_t)(bc * 8) * 1024 + d;
#pragma unroll
    for (int n = 0; n < 8; ++n) {
        float v = cc[n];
        __half h = __float2half(v);
        float hl = __half2float(h);
        float r = v - hl;                 // fp16 residual
        oh[(size_t)n * 1024]       = h;
        oh[(size_t)n * 1024 + 512] = __float2half(r);
        o8[(size_t)n * 1024]       = to_e4m3(r * 4096.0f);   // Al * 2^12
        o8[(size_t)n * 1024 + 512] = to_e4m3(hl);            // Ah
    }
}

// ---------------------------------------------------------------------------
// Kernel 2: W -> Wh (fp16) and [Wh | Wl*2^12] (e4m3)
// ---------------------------------------------------------------------------
__global__ __launch_bounds__(256) void wconv_kernel(const float* __restrict__ W) {
    int t = blockIdx.x * blockDim.x + threadIdx.x;
    int e = t >> 9, k = t & 511;
    float w = W[(size_t)e * 512 + k];
    __half h = __float2half(w);
    float hl = __half2float(h);
    float r = w - hl;
    g_Bh[(size_t)e * 512 + k]        = h;
    g_B8[(size_t)e * 1024 + k]       = to_e4m3(hl);            // Wh
    g_B8[(size_t)e * 1024 + 512 + k] = to_e4m3(r * 4096.0f);   // Wl * 2^12
}

// ---------------------------------------------------------------------------
// Kernel 3: mixed fp8/fp16 GEMM (128x128 tile) + fused gate/threshold/iwpt/+x.
// ---------------------------------------------------------------------------
__global__ void __launch_bounds__(TPB, 2) gemm_kernel(
        const float* __restrict__ bias, const float* __restrict__ thrp,
        const float* __restrict__ x, float* __restrict__ out) {
    extern __shared__ __align__(16) char dsm[];

    const int tid = threadIdx.x, wid = tid >> 5, lane = tid & 31;
    const int wm = wid & 1, wn = wid >> 1;          // 2 x 4 warp grid
    const int colTile = blockIdx.x * 128;
    const int rowTile = blockIdx.y * 128;
    const uint32_t sbase = smem_u32(dsm);

    float acc[4][4][4];
#pragma unroll
    for (int i = 0; i < 4; ++i)
#pragma unroll
        for (int j = 0; j < 4; ++j)
#pragma unroll
            for (int q = 0; q < 4; ++q) acc[i][j][q] = 0.f;

    auto load_stage = [&](int c, int st) {
        uint32_t sA = sbase + st * STAGE_BYTES;
        uint32_t sB = sA + 128 * RSTRIDE;
#pragma unroll
        for (int p = 0; p < 8; ++p) {
            int q = tid + p * TPB;                  // 0..2047
            int mat = q >> 10, idx = q & 1023;
            int r = idx >> 3, ch = idx & 7;         // 8 x 16B chunks per row
            uint32_t dst = (mat ? sB : sA) + r * RSTRIDE + ch * 16;
            if (c < 8) {                            // fp8 phase: 128 bytes/row
                int kb = c * 128 + ch * 16;
                const uint8_t* src = mat ? g_B8 + (size_t)(colTile + r) * 1024 + kb
                                         : g_A8 + (size_t)(rowTile + r) * 1024 + kb;
                cp16(dst, src);
            } else {                                // fp16 phase: 64 halfs/row
                int kh = (c - 8) * 64 + ch * 8;
                const __half* src = mat ? g_Bh + (size_t)(colTile + r) * 512 + kh
                                        : g_Ah + (size_t)(rowTile + r) * 1024 + kh;
                cp16(dst, src);
            }
        }
        asm volatile("cp.async.commit_group;" ::: "memory");
    };

    load_stage(0, 0);
    load_stage(1, 1);

    const int lrow = lane & 15;
    const int lcolB = (lane >> 4) << 4;             // byte offset within 32B k-chunk

    for (int c = 0; c < NKITER; ++c) {
        int st = c % 3;
        if (c < NKITER - 1)
            asm volatile("cp.async.wait_group 1;" ::: "memory");
        else
            asm volatile("cp.async.wait_group 0;" ::: "memory");
        __syncthreads();
        if (c + 2 < NKITER) load_stage(c + 2, (c + 2) % 3);

        uint32_t sA = sbase + st * STAGE_BYTES;
        uint32_t sB = sA + 128 * RSTRIDE;
#pragma unroll
        for (int kk = 0; kk < 4; ++kk) {
            const int kb0 = kk * 32 + lcolB;        // 32 bytes per kk-step
            uint32_t af[4][4];
#pragma unroll
            for (int mt = 0; mt < 4; ++mt) {
                int row = wm * 64 + mt * 16 + lrow;
                ldm_x4(af[mt][0], af[mt][1], af[mt][2], af[mt][3],
                       sA + row * RSTRIDE + kb0);
            }
            uint32_t bf[2][4];
#pragma unroll
            for (int nn = 0; nn < 2; ++nn) {
                int row = wn * 32 + nn * 16 + lrow;
                ldm_x4(bf[nn][0], bf[nn][1], bf[nn][2], bf[nn][3],
                       sB + row * RSTRIDE + kb0);
            }
            if (c < 8) {
#pragma unroll
                for (int mt = 0; mt < 4; ++mt)
#pragma unroll
                    for (int nt = 0; nt < 4; ++nt) {
                        int nn = nt >> 1, hi = nt & 1;
                        mma_f8(acc[mt][nt], af[mt], bf[nn][hi], bf[nn][2 + hi]);
                    }
            } else {
#pragma unroll
                for (int mt = 0; mt < 4; ++mt)
#pragma unroll
                    for (int nt = 0; nt < 4; ++nt) {
                        int nn = nt >> 1, hi = nt & 1;
                        mma_f16(acc[mt][nt], af[mt], bf[nn][hi], bf[nn][2 + hi]);
                    }
            }
        }
        if (c == 7) {                               // end of fp8 phase: undo 2^12
#pragma unroll
            for (int i = 0; i < 4; ++i)
#pragma unroll
                for (int j = 0; j < 4; ++j)
#pragma unroll
                    for (int q = 0; q < 4; ++q) acc[i][j][q] *= 2.44140625e-4f;
        }
    }
    __syncthreads();

    // ---------------- epilogue ----------------
    float* sG    = (float*)dsm;                     // [128][129]
    float* sBias = (float*)(dsm + 128 * 129 * 4);
    for (int i = tid; i < 128; i += TPB) sBias[i] = bias[colTile + i];
    __syncthreads();

    const float thr = thrp[0];
    const int rq = lane >> 2, cq = (lane & 3) * 2;

#pragma unroll
    for (int mt = 0; mt < 4; ++mt)
#pragma unroll
        for (int nt = 0; nt < 4; ++nt)
#pragma unroll
            for (int h = 0; h < 2; ++h) {
                int row = wm * 64 + mt * 16 + rq + h * 8;
                int col = wn * 32 + nt * 8 + cq;
                __half2 hh = *(const __half2*)(g_Ah + (size_t)(rowTile + row) * 1024 +
                                               colTile + col);
                __half2 ll = *(const __half2*)(g_Ah + (size_t)(rowTile + row) * 1024 +
                                               512 + colTile + col);
                float co0 = __half2float(hh.x) + __half2float(ll.x);
                float co1 = __half2float(hh.y) + __half2float(ll.y);
                float l0 = acc[mt][nt][h * 2 + 0] + sBias[col];
                float l1 = acc[mt][nt][h * 2 + 1] + sBias[col + 1];
                float g0 = co0 / (1.0f + __expf(-l0));
                float g1 = co1 / (1.0f + __expf(-l1));
                if (fabsf(g0) < thr) g0 = 0.0f;
                if (fabsf(g1) < thr) g1 = 0.0f;
                sG[row * 129 + col]     = g0;
                sG[row * 129 + col + 1] = g1;
            }
    __syncthreads();

    const float s2 = 0.70710678118654752440f;
    const int bcBase = rowTile >> 3;
#pragma unroll
    for (int p = 0; p < 8; ++p) {
        int t = tid + p * TPB;           // 0..2047
        int gl = t >> 7, d = t & 127;
        float gv[8];
#pragma unroll
        for (int n = 0; n < 8; ++n) gv[n] = sG[(gl * 8 + n) * 129 + d];

        float p0 = (gv[0] + gv[1]) * s2, p1 = (gv[0] - gv[1]) * s2;
        float p2 = (gv[2] + gv[3]) * s2, p3 = (gv[2] - gv[3]) * s2;
        float p4 = (gv[4] + gv[5]) * s2, p5 = (gv[4] - gv[5]) * s2;
        float p6 = (gv[6] + gv[7]) * s2, p7 = (gv[6] - gv[7]) * s2;
        float A0 = (p0 + p2) * s2, A1 = (p0 - p2) * s2;
        float A2 = (p1 + p3) * s2, A3 = (p1 - p3) * s2;
        float D0 = (p4 + p6) * s2, D1 = (p4 - p6) * s2;
        float D2 = (p5 + p7) * s2, D3 = (p5 - p7) * s2;
        float r0 = (A0 + D0) * s2, r1 = (A0 - D0) * s2;
        float r2 = (A1 + D1) * s2, r3 = (A1 - D1) * s2;
        float r4 = (A2 + D2) * s2, r5 = (A2 - D2) * s2;
        float r6 = (A3 + D3) * s2, r7 = (A3 - D3) * s2;

        size_t off = (size_t)(bcBase + gl) * 4096 + (size_t)(colTile + d) * 8;
        float4 x0 = *(const float4*)(x + off);
        float4 x1 = *(const float4*)(x + off + 4);
        *(float4*)(out + off)     = make_float4(r0 + x0.x, r1 + x0.y, r2 + x0.z, r3 + x0.w);
        *(float4*)(out + off + 4) = make_float4(r4 + x1.x, r5 + x1.y, r6 + x1.z, r7 + x1.w);
    }
}

// ---------------------------------------------------------------------------
extern "C" void kernel_launch(void* const* d_in, const int* in_sizes, int n_in,
                              void* d_out, int out_size) {
    const float* x   = (const float*)d_in[0];
    const float* W   = (const float*)d_in[1];
    const float* b   = (const float*)d_in[2];
    const float* thr = (const float*)d_in[3];
    float* out = (float*)d_out;

    cudaFuncSetAttribute(gemm_kernel, cudaFuncAttributeMaxDynamicSharedMemorySize,
                         DSMEM_BYTES);

    wpt_split_kernel<<<4096, 256>>>(x);
    wconv_kernel<<<1024, 256>>>(W);
    dim3 grid(KD / 128, M_TOTAL / 128);   // (4, 128)
    gemm_kernel<<<grid, TPB, DSMEM_BYTES>>>(b, thr, x, out);
}

// round 8
// speedup vs baseline: 1.0023x; 1.0023x over previous
#include <cuda_runtime.h>
#include <cuda_fp16.h>
#include <cuda_fp8.h>
#include <cstdint>

// WaveletGatedNet (sm_100 plain): mixed fp8/fp16 split GEMM on mma.sync.
//   logits = Ah*Wh (fp16, K=512)  +  2^-12 * { [Al*2^12|Ah] . [Wh|Wl*2^12] } (fp8 e4m3, K=1024)
// Equivalent MMA cost 64 units vs 96 for bf16x3. Residual logit err ~5e-5.

#define KD 512
#define TPB 256
#define M_TOTAL 16384
#define NKITER 16                 // 8 fp8 iters (K=1024, 128B/row) + 8 fp16 iters (K=512)
#define RSTRIDE 144               // bytes per smem row (128 data + 16 pad)
#define STAGE_BYTES (2 * 128 * RSTRIDE)       // A + B tiles (36864)
#define DSMEM_BYTES (3 * STAGE_BYTES)         // 110592 (> epilogue's 66560)

__device__ __half  g_Ah[(size_t)M_TOTAL * 1024];  // [row][0:512)=Ah, [512:1024)=Al (fp16)
__device__ uint8_t g_A8[(size_t)M_TOTAL * 1024];  // [row][0:512)=e4m3(Al*2^12), [512:1024)=e4m3(Ah)
__device__ __half  g_Bh[(size_t)KD * 512];        // [n][k] = Wh fp16
__device__ uint8_t g_B8[(size_t)KD * 1024];       // [n][0:512)=e4m3(Wh), [512:1024)=e4m3(Wl*2^12)

static __device__ __forceinline__ uint32_t smem_u32(const void* p) {
    uint32_t a;
    asm("{ .reg .u64 t; cvta.to.shared.u64 t, %1; cvt.u32.u64 %0, t; }"
        : "=r"(a) : "l"(p));
    return a;
}
static __device__ __forceinline__ void cp16(uint32_t dst, const void* src) {
    asm volatile("cp.async.cg.shared.global [%0], [%1], 16;"
                 :: "r"(dst), "l"(__cvta_generic_to_global(src)) : "memory");
}
static __device__ __forceinline__ void ldm_x4(uint32_t& r0, uint32_t& r1,
                                              uint32_t& r2, uint32_t& r3, uint32_t a) {
    asm volatile("ldmatrix.sync.aligned.m8n8.x4.shared.b16 {%0,%1,%2,%3}, [%4];"
                 : "=r"(r0), "=r"(r1), "=r"(r2), "=r"(r3) : "r"(a));
}
static __device__ __forceinline__ void mma_f16(float* c, const uint32_t* a,
                                               uint32_t b0, uint32_t b1) {
    asm volatile("mma.sync.aligned.m16n8k16.row.col.f32.f16.f16.f32 "
                 "{%0,%1,%2,%3}, {%4,%5,%6,%7}, {%8,%9}, {%0,%1,%2,%3};"
                 : "+f"(c[0]), "+f"(c[1]), "+f"(c[2]), "+f"(c[3])
                 : "r"(a[0]), "r"(a[1]), "r"(a[2]), "r"(a[3]), "r"(b0), "r"(b1));
}
static __device__ __forceinline__ void mma_f8(float* c, const uint32_t* a,
                                              uint32_t b0, uint32_t b1) {
    asm volatile("mma.sync.aligned.m16n8k32.row.col.f32.e4m3.e4m3.f32 "
                 "{%0,%1,%2,%3}, {%4,%5,%6,%7}, {%8,%9}, {%0,%1,%2,%3};"
                 : "+f"(c[0]), "+f"(c[1]), "+f"(c[2]), "+f"(c[3])
                 : "r"(a[0]), "r"(a[1]), "r"(a[2]), "r"(a[3]), "r"(b0), "r"(b1));
}
static __device__ __forceinline__ uint8_t to_e4m3(float f) {
    return (uint8_t)__nv_cvt_float_to_fp8(f, __NV_SATFINITE, __NV_E4M3);
}

// ---------------------------------------------------------------------------
// Kernel 1: Haar WPT + fp16 hi/lo split + fp8 correction operands.
// ---------------------------------------------------------------------------
__global__ __launch_bounds__(256) void wpt_split_kernel(const float* __restrict__ x) {
    const float s = 0.70710678118654752440f;
    int t = blockIdx.x * blockDim.x + threadIdx.x;
    int bc = t >> 9, d = t & 511;

    const float4* xp = (const float4*)(x + (size_t)bc * 4096 + (size_t)d * 8);
    float4 v0 = xp[0], v1 = xp[1];

    float a0 = (v0.x + v0.y) * s, d0 = (v0.x - v0.y) * s;
    float a1 = (v0.z + v0.w) * s, d1 = (v0.z - v0.w) * s;
    float a2 = (v1.x + v1.y) * s, d2 = (v1.x - v1.y) * s;
    float a3 = (v1.z + v1.w) * s, d3 = (v1.z - v1.w) * s;
    float aa0 = (a0 + a1) * s, da0 = (a0 - a1) * s;
    float aa1 = (a2 + a3) * s, da1 = (a2 - a3) * s;
    float ad0 = (d0 + d1) * s, dd0 = (d0 - d1) * s;
    float ad1 = (d2 + d3) * s, dd1 = (d2 - d3) * s;
    float cc[8];
    cc[0] = (aa0 + aa1) * s; cc[1] = (aa0 - aa1) * s;
    cc[2] = (da0 + da1) * s; cc[3] = (da0 - da1) * s;
    cc[4] = (ad0 + ad1) * s; cc[5] = (ad0 - ad1) * s;
    cc[6] = (dd0 + dd1) * s; cc[7] = (dd0 - dd1) * s;

    __half*  oh = g_Ah + (size_t)(bc * 8) * 1024 + d;
    uint8_t* o8 = g_A8 + (size_t)(bc * 8) * 1024 + d;
#pragma unroll
    for (int n = 0; n < 8; ++n) {
        float v = cc[n];
        __half h = __float2half(v);
        float hl = __half2float(h);
        float r = v - hl;                 // fp16 residual
        oh[(size_t)n * 1024]       = h;
        oh[(size_t)n * 1024 + 512] = __float2half(r);
        o8[(size_t)n * 1024]       = to_e4m3(r * 4096.0f);   // Al * 2^12
        o8[(size_t)n * 1024 + 512] = to_e4m3(hl);            // Ah
    }
}

// ---------------------------------------------------------------------------
// Kernel 2: W -> Wh (fp16) and [Wh | Wl*2^12] (e4m3)
// ---------------------------------------------------------------------------
__global__ __launch_bounds__(256) void wconv_kernel(const float* __restrict__ W) {
    int t = blockIdx.x * blockDim.x + threadIdx.x;
    int e = t >> 9, k = t & 511;
    float w = W[(size_t)e * 512 + k];
    __half h = __float2half(w);
    float hl = __half2float(h);
    float r = w - hl;
    g_Bh[(size_t)e * 512 + k]        = h;
    g_B8[(size_t)e * 1024 + k]       = to_e4m3(hl);            // Wh
    g_B8[(size_t)e * 1024 + 512 + k] = to_e4m3(r * 4096.0f);   // Wl * 2^12
}

// ---------------------------------------------------------------------------
// Kernel 3: mixed fp8/fp16 GEMM (128x128 tile) + fused gate/threshold/iwpt/+x.
// ---------------------------------------------------------------------------
__global__ void __launch_bounds__(TPB, 2) gemm_kernel(
        const float* __restrict__ bias, const float* __restrict__ thrp,
        const float* __restrict__ x, float* __restrict__ out) {
    extern __shared__ __align__(16) char dsm[];

    const int tid = threadIdx.x, wid = tid >> 5, lane = tid & 31;
    const int wm = wid & 1, wn = wid >> 1;          // 2 x 4 warp grid
    const int colTile = blockIdx.x * 128;
    const int rowTile = blockIdx.y * 128;
    const uint32_t sbase = smem_u32(dsm);

    float acc[4][4][4];
#pragma unroll
    for (int i = 0; i < 4; ++i)
#pragma unroll
        for (int j = 0; j < 4; ++j)
#pragma unroll
            for (int q = 0; q < 4; ++q) acc[i][j][q] = 0.f;

    auto load_stage = [&](int c, int st) {
        uint32_t sA = sbase + st * STAGE_BYTES;
        uint32_t sB = sA + 128 * RSTRIDE;
#pragma unroll
        for (int p = 0; p < 8; ++p) {
            int q = tid + p * TPB;                  // 0..2047
            int mat = q >> 10, idx = q & 1023;
            int r = idx >> 3, ch = idx & 7;         // 8 x 16B chunks per row
            uint32_t dst = (mat ? sB : sA) + r * RSTRIDE + ch * 16;
            if (c < 8) {                            // fp8 phase: 128 bytes/row
                int kb = c * 128 + ch * 16;
                const uint8_t* src = mat ? g_B8 + (size_t)(colTile + r) * 1024 + kb
                                         : g_A8 + (size_t)(rowTile + r) * 1024 + kb;
                cp16(dst, src);
            } else {                                // fp16 phase: 64 halfs/row
                int kh = (c - 8) * 64 + ch * 8;
                const __half* src = mat ? g_Bh + (size_t)(colTile + r) * 512 + kh
                                        : g_Ah + (size_t)(rowTile + r) * 1024 + kh;
                cp16(dst, src);
            }
        }
        asm volatile("cp.async.commit_group;" ::: "memory");
    };

    load_stage(0, 0);
    load_stage(1, 1);

    const int lrow = lane & 15;
    const int lcolB = (lane >> 4) << 4;             // byte offset within 32B k-chunk

    for (int c = 0; c < NKITER; ++c) {
        int st = c % 3;
        if (c < NKITER - 1)
            asm volatile("cp.async.wait_group 1;" ::: "memory");
        else
            asm volatile("cp.async.wait_group 0;" ::: "memory");
        __syncthreads();
        if (c + 2 < NKITER) load_stage(c + 2, (c + 2) % 3);

        uint32_t sA = sbase + st * STAGE_BYTES;
        uint32_t sB = sA + 128 * RSTRIDE;
#pragma unroll
        for (int kk = 0; kk < 4; ++kk) {
            const int kb0 = kk * 32 + lcolB;        // 32 bytes per kk-step
            uint32_t af[4][4];
#pragma unroll
            for (int mt = 0; mt < 4; ++mt) {
                int row = wm * 64 + mt * 16 + lrow;
                ldm_x4(af[mt][0], af[mt][1], af[mt][2], af[mt][3],
                       sA + row * RSTRIDE + kb0);
            }
            uint32_t bf[2][4];
#pragma unroll
            for (int nn = 0; nn < 2; ++nn) {
                int row = wn * 32 + nn * 16 + lrow;
                ldm_x4(bf[nn][0], bf[nn][1], bf[nn][2], bf[nn][3],
                       sB + row * RSTRIDE + kb0);
            }
            if (c < 8) {
#pragma unroll
                for (int mt = 0; mt < 4; ++mt)
#pragma unroll
                    for (int nt = 0; nt < 4; ++nt) {
                        int nn = nt >> 1, hi = nt & 1;
                        mma_f8(acc[mt][nt], af[mt], bf[nn][hi], bf[nn][2 + hi]);
                    }
            } else {
#pragma unroll
                for (int mt = 0; mt < 4; ++mt)
#pragma unroll
                    for (int nt = 0; nt < 4; ++nt) {
                        int nn = nt >> 1, hi = nt & 1;
                        mma_f16(acc[mt][nt], af[mt], bf[nn][hi], bf[nn][2 + hi]);
                    }
            }
        }
        if (c == 7) {                               // end of fp8 phase: undo 2^12
#pragma unroll
            for (int i = 0; i < 4; ++i)
#pragma unroll
                for (int j = 0; j < 4; ++j)
#pragma unroll
                    for (int q = 0; q < 4; ++q) acc[i][j][q] *= 2.44140625e-4f;
        }
    }
    __syncthreads();

    // ---------------- epilogue ----------------
    float* sG    = (float*)dsm;                     // [128][129]
    float* sBias = (float*)(dsm + 128 * 129 * 4);
    for (int i = tid; i < 128; i += TPB) sBias[i] = bias[colTile + i];
    __syncthreads();

    const float thr = thrp[0];
    const int rq = lane >> 2, cq = (lane & 3) * 2;

#pragma unroll
    for (int mt = 0; mt < 4; ++mt)
#pragma unroll
        for (int nt = 0; nt < 4; ++nt)
#pragma unroll
            for (int h = 0; h < 2; ++h) {
                int row = wm * 64 + mt * 16 + rq + h * 8;
                int col = wn * 32 + nt * 8 + cq;
                __half2 hh = *(const __half2*)(g_Ah + (size_t)(rowTile + row) * 1024 +
                                               colTile + col);
                __half2 ll = *(const __half2*)(g_Ah + (size_t)(rowTile + row) * 1024 +
                                               512 + colTile + col);
                float co0 = __half2float(hh.x) + __half2float(ll.x);
                float co1 = __half2float(hh.y) + __half2float(ll.y);
                float l0 = acc[mt][nt][h * 2 + 0] + sBias[col];
                float l1 = acc[mt][nt][h * 2 + 1] + sBias[col + 1];
                float g0 = co0 / (1.0f + __expf(-l0));
                float g1 = co1 / (1.0f + __expf(-l1));
                if (fabsf(g0) < thr) g0 = 0.0f;
                if (fabsf(g1) < thr) g1 = 0.0f;
                sG[row * 129 + col]     = g0;
                sG[row * 129 + col + 1] = g1;
            }
    __syncthreads();

    const float s2 = 0.70710678118654752440f;
    const int bcBase = rowTile >> 3;
#pragma unroll
    for (int p = 0; p < 8; ++p) {
        int t = tid + p * TPB;           // 0..2047
        int gl = t >> 7, d = t & 127;
        float gv[8];
#pragma unroll
        for (int n = 0; n < 8; ++n) gv[n] = sG[(gl * 8 + n) * 129 + d];

        float p0 = (gv[0] + gv[1]) * s2, p1 = (gv[0] - gv[1]) * s2;
        float p2 = (gv[2] + gv[3]) * s2, p3 = (gv[2] - gv[3]) * s2;
        float p4 = (gv[4] + gv[5]) * s2, p5 = (gv[4] - gv[5]) * s2;
        float p6 = (gv[6] + gv[7]) * s2, p7 = (gv[6] - gv[7]) * s2;
        float A0 = (p0 + p2) * s2, A1 = (p0 - p2) * s2;
        float A2 = (p1 + p3) * s2, A3 = (p1 - p3) * s2;
        float D0 = (p4 + p6) * s2, D1 = (p4 - p6) * s2;
        float D2 = (p5 + p7) * s2, D3 = (p5 - p7) * s2;
        float r0 = (A0 + D0) * s2, r1 = (A0 - D0) * s2;
        float r2 = (A1 + D1) * s2, r3 = (A1 - D1) * s2;
        float r4 = (A2 + D2) * s2, r5 = (A2 - D2) * s2;
        float r6 = (A3 + D3) * s2, r7 = (A3 - D3) * s2;

        size_t off = (size_t)(bcBase + gl) * 4096 + (size_t)(colTile + d) * 8;
        float4 x0 = *(const float4*)(x + off);
        float4 x1 = *(const float4*)(x + off + 4);
        *(float4*)(out + off)     = make_float4(r0 + x0.x, r1 + x0.y, r2 + x0.z, r3 + x0.w);
        *(float4*)(out + off + 4) = make_float4(r4 + x1.x, r5 + x1.y, r6 + x1.z, r7 + x1.w);
    }
}

// ---------------------------------------------------------------------------
extern "C" void kernel_launch(void* const* d_in, const int* in_sizes, int n_in,
                              void* d_out, int out_size) {
    const float* x   = (const float*)d_in[0];
    const float* W   = (const float*)d_in[1];
    const float* b   = (const float*)d_in[2];
    const float* thr = (const float*)d_in[3];
    float* out = (float*)d_out;

    cudaFuncSetAttribute(gemm_kernel, cudaFuncAttributeMaxDynamicSharedMemorySize,
                         DSMEM_BYTES);

    wpt_split_kernel<<<4096, 256>>>(x);
    wconv_kernel<<<1024, 256>>>(W);
    dim3 grid(KD / 128, M_TOTAL / 128);   // (4, 128)
    gemm_kernel<<<grid, TPB, DSMEM_BYTES>>>(b, thr, x, out);
}